// round 10
// baseline (speedup 1.0000x reference)
#include <cuda_runtime.h>

#define NMAX 50000
#define C    91
#define NC   90
#define TT   3
#define NDET 100
#define CAP  2048
#define NMS_T 512
#define BATCH 8
#define NEG_INF (__int_as_float(0xff800000))
#define BBOX_CLIP 4.135166556742356f   // log(1000/16)

// ---------------- scratch (static device globals; no allocation) ----------------
__device__ int    d_cnt[NC];
__device__ int    d_cidx [(size_t)NC * NMAX];
__device__ float  d_cscore[(size_t)NC * NMAX];
__device__ float4 d_cbox [(size_t)NC * NMAX];

// ---------------- helpers ----------------
__device__ __forceinline__ float read_dim(const void* p) {
    int v = *(const int*)p;
    if (v > 0 && v < 1000000) return (float)v;
    return *(const float*)p;
}

__device__ __forceinline__ float4 decode4(float4 d, float4 b) {
    float w  = b.z - b.x;
    float h  = b.w - b.y;
    float cx = b.x + 0.5f * w;
    float cy = b.y + 0.5f * h;
    float dx = d.x / 10.0f;
    float dy = d.y / 10.0f;
    float dw = fminf(d.z / 5.0f, BBOX_CLIP);
    float dh = fminf(d.w / 5.0f, BBOX_CLIP);
    float pcx = dx * w + cx;
    float pcy = dy * h + cy;
    float pw  = expf(dw) * w;
    float ph  = expf(dh) * h;
    float4 r;
    r.x = pcx - 0.5f * pw;
    r.y = pcy - 0.5f * ph;
    r.z = pcx + 0.5f * pw;
    r.w = pcy + 0.5f * ph;
    return r;
}

__device__ __forceinline__ float4 clip4(float4 b, float W, float H) {
    float4 r;
    r.x = fminf(fmaxf(b.x, 0.0f), W);
    r.y = fminf(fmaxf(b.y, 0.0f), H);
    r.z = fminf(fmaxf(b.z, 0.0f), W);
    r.w = fminf(fmaxf(b.w, 0.0f), H);
    return r;
}

__device__ __forceinline__ bool iou_gt(float4 c, float ac, float4 bb, float k1) {
    float lx = fmaxf(bb.x, c.x), ly = fmaxf(bb.y, c.y);
    float rx = fminf(bb.z, c.z), ry = fminf(bb.w, c.w);
    float iw = fmaxf(rx - lx, 0.0f), ih = fmaxf(ry - ly, 0.0f);
    float inter = iw * ih;
    float t = k1 + ac - inter;
    return inter + inter > t;        // iou > 0.5
}

// ---------------- kernel 1: fused softmax + filter + decode + compact ----------------
__global__ void __launch_bounds__(256, 8)
fused_cand(const float* __restrict__ logits,
           const float4* __restrict__ boxreg,   // [N, C] float4
           const float4* __restrict__ prop,     // [N]
           const void* hp, const void* wp, int N) {
    int warp = (blockIdx.x * blockDim.x + threadIdx.x) >> 5;
    int lane = threadIdx.x & 31;
    if (warp >= N) return;
    const float* row = logits + (size_t)warp * C;
    float v0 = row[lane];
    float v1 = row[lane + 32];
    float v2 = (lane < C - 64) ? row[lane + 64] : NEG_INF;
    float m = fmaxf(v0, fmaxf(v1, v2));
    #pragma unroll
    for (int o = 16; o; o >>= 1) m = fmaxf(m, __shfl_xor_sync(~0u, m, o));
    float e0 = expf(v0 - m);
    float e1 = expf(v1 - m);
    float e2 = (lane < C - 64) ? expf(v2 - m) : 0.0f;
    float s = e0 + e1 + e2;
    #pragma unroll
    for (int o = 16; o; o >>= 1) s += __shfl_xor_sync(~0u, s, o);

    // coarse filter (superset; exact recheck with identical FP expr below)
    float thr = 0.0499f * s;
    bool a0 = (lane >= 1) && (e0 >= thr);
    bool a1 = (e1 >= thr);
    bool a2 = (lane < C - 64) && (e2 >= thr);
    if (!__any_sync(~0u, a0 | a1 | a2)) return;

    float4 pr = prop[warp];
    float W = read_dim(wp), H = read_dim(hp);

    #pragma unroll
    for (int slot = 0; slot < 3; ++slot) {
        bool act = slot == 0 ? a0 : (slot == 1 ? a1 : a2);
        if (!act) continue;
        float e = slot == 0 ? e0 : (slot == 1 ? e1 : e2);
        float p = e / s;                 // exact
        if (p < 0.05f) continue;         // exact recheck
        int c = lane + 32 * slot;        // class index 1..90
        float4 cb = clip4(decode4(boxreg[(size_t)warp * C + c], pr), W, H);
        float ws = cb.z - cb.x, hs = cb.w - cb.y;
        if (ws < 1.0f || hs < 1.0f) continue;
        int j = c - 1;
        int sl = atomicAdd(&d_cnt[j], 1);
        size_t off = (size_t)j * NMAX + sl;
        d_cidx[off]   = warp;
        d_cscore[off] = p;
        d_cbox[off]   = cb;
    }
}

// ---------------- kernel 2: sorted batched-greedy NMS + fused output ----------------
__global__ void __launch_bounds__(NMS_T, 1)
nms_out_kernel(const float* __restrict__ logits,
               const float4* __restrict__ boxreg,
               const float4* __restrict__ trajreg,   // [T, N, C] float4
               const float4* __restrict__ prop,
               const void* hp, const void* wp,
               float* __restrict__ out, int N) {
    int j = blockIdx.x;
    int cnt = d_cnt[j];
    if (cnt > CAP) cnt = CAP;
    size_t base = (size_t)j * NMAX;
    int tid = threadIdx.x, lane = tid & 31;

    extern __shared__ unsigned char smem_raw[];
    unsigned long long* s_key = (unsigned long long*)smem_raw;        // CAP * 8
    float4* s_box  = (float4*)(s_key + CAP);                          // CAP * 16
    float*  s_area = (float*)(s_box + CAP);                           // CAP * 4
    unsigned char* s_supp = (unsigned char*)(s_area + CAP);           // CAP * 1

    __shared__ float4 s_batch[BATCH];
    __shared__ float  s_batcha[BATCH];
    __shared__ int    s_bn, s_lo;
    __shared__ int    s_keep[NDET];

    if (cnt == 0) {
        for (int r = tid; r < NDET; r += NMS_T) s_keep[r] = -1;
    } else {
        int n = 1;
        while (n < cnt) n <<= 1;
        if (n < 2) n = 2;

        // key: (score_bits << 32) | ~slot  -> desc sort: score desc, slot asc on ties
        for (int i = tid; i < n; i += NMS_T) {
            s_key[i] = (i < cnt)
                ? (((unsigned long long)__float_as_uint(d_cscore[base + i]) << 32)
                   | (unsigned)(~(unsigned)i))
                : 0ull;
        }

        // bitonic sort, descending; pair-index formulation.
        // st <= 32 phases are warp-private: each owned pair p in [32w,32w+32)
        // (mod NMS_T strides) touches one 64-element block -> __syncwarp suffices.
        bool prev_big = true;   // key init wrote cross-warp
        for (int k = 2; k <= n; k <<= 1) {
            for (int st = k >> 1; st > 0; st >>= 1) {
                bool big = (st >= 64);
                if (big || prev_big) __syncthreads(); else __syncwarp();
                for (int p = tid; p < (n >> 1); p += NMS_T) {
                    int i = 2 * p - (p & (st - 1));
                    int l = i + st;
                    unsigned long long a = s_key[i], b = s_key[l];
                    bool desc = ((i & k) == 0);
                    if (desc ? (a < b) : (a > b)) { s_key[i] = b; s_key[l] = a; }
                }
                prev_big = big;
            }
        }
        __syncthreads();

        // gather boxes in sorted order
        for (int i = tid; i < cnt; i += NMS_T) {
            int sl = (int)(~(unsigned)(s_key[i] & 0xffffffffu));
            float4 b = d_cbox[base + sl];
            s_box[i]  = b;
            s_area[i] = (b.z - b.x) * (b.w - b.y);
            s_supp[i] = 0;
        }
        __syncthreads();

        // batched greedy scan (warp 0) + block sweep
        int it = 0, cursor = 0;
        bool exhausted = false;

        while (true) {
            if (tid < 32) {
                int bn = 0, first = -1;
                int w0 = -1;
                unsigned ok = 0;
                float4 c = make_float4(0.f, 0.f, 0.f, 0.f);
                float ac = 0.f;

                while (bn < BATCH && it < NDET) {
                    if (ok == 0) {
                        w0 = (w0 < 0) ? (cursor & ~31) : (w0 + 32);
                        if (w0 >= cnt) { exhausted = true; break; }
                        int i = w0 + lane;
                        int ii = (i < cnt) ? i : (cnt - 1);
                        c = s_box[ii]; ac = s_area[ii];
                        bool alive = (i >= cursor) && (i < cnt) && (s_supp[i] == 0);
                        #pragma unroll
                        for (int b = 0; b < BATCH; ++b)
                            if (b < bn)
                                alive = alive && !iou_gt(c, ac, s_batch[b], s_batcha[b]);
                        ok = __ballot_sync(~0u, alive);
                        continue;
                    }
                    int t = __ffs(ok) - 1;
                    int p = w0 + t;
                    float4 pb = s_box[p];
                    float  pa = s_area[p] + 1e-9f;
                    s_batch[bn] = pb;            // all lanes write same value
                    s_batcha[bn] = pa;
                    if (lane == 0)
                        s_keep[it] = (int)(~(unsigned)(s_key[p] & 0xffffffffu));
                    if (bn == 0) first = p;
                    ++bn; ++it;
                    cursor = p + 1;
                    bool kill = iou_gt(c, ac, pb, pa);
                    ok &= __ballot_sync(~0u, !kill);
                    ok &= ~((2u << t) - 1u);     // clear bits <= t
                }
                if (exhausted)
                    for (int r = it + lane; r < NDET; r += 32)
                        s_keep[r] = -1;
                if (lane == 0) {
                    s_bn = (it < NDET && !exhausted) ? bn : 0;
                    s_lo = first;
                }
            }
            __syncthreads();
            int bn = s_bn;
            if (bn == 0) break;
            int lo = s_lo;
            for (int i = lo + 1 + tid; i < cnt; i += NMS_T) {
                if (!s_supp[i]) {
                    float4 c = s_box[i];
                    float ac = s_area[i];
                    bool kill = false;
                    #pragma unroll
                    for (int b = 0; b < BATCH; ++b)
                        if (b < bn)
                            kill = kill || iou_gt(c, ac, s_batch[b], s_batcha[b]);
                    if (kill) s_supp[i] = 1;
                }
            }
            __syncthreads();
        }
    }
    __syncthreads();

    // ---------------- fused output phase ----------------
    float W = read_dim(wp), H = read_dim(hp);
    const int M = NC * NDET;
    for (int s = tid; s < NDET; s += NMS_T) {
        int o = j * NDET + s;
        int slot = s_keep[s];
        int k = (slot >= 0) ? d_cidx[base + slot] : 0;

        // independent gathers issued up front
        float4 pr  = prop[k];
        float4 td0 = trajreg[((size_t)0 * N + k) * C + (j + 1)];
        float4 td1 = trajreg[((size_t)1 * N + k) * C + (j + 1)];
        float4 td2 = trajreg[((size_t)2 * N + k) * C + (j + 1)];

        float4 cb; float p; int vld;
        if (slot >= 0) {
            cb  = d_cbox[base + slot];       // already clipped
            p   = d_cscore[base + slot];
            vld = 1;
        } else {
            cb = clip4(decode4(boxreg[j + 1], pr), W, H);
            const float* lg0 = logits;
            float m = NEG_INF;
            for (int c = 0; c < C; ++c) m = fmaxf(m, lg0[c]);
            float ss = 0.0f;
            for (int c = 0; c < C; ++c) ss += expf(lg0[c] - m);
            p = expf(lg0[j + 1] - m) / ss;
            vld = 0;
        }

        out[o * 4 + 0] = cb.x;
        out[o * 4 + 1] = cb.y;
        out[o * 4 + 2] = cb.z;
        out[o * 4 + 3] = cb.w;
        out[4 * M + o] = (float)(j + 1);
        out[5 * M + o] = p;

        // trajectory chain: carry UNclipped, emit clipped
        float4 nb0 = decode4(td0, pr);
        float4 nb1 = decode4(td1, nb0);
        float4 nb2 = decode4(td2, nb1);
        float4 cn0 = clip4(nb0, W, H);
        float4 cn1 = clip4(nb1, W, H);
        float4 cn2 = clip4(nb2, W, H);
        int fo0 = 6 * M + (0 * M + o) * 4;
        int fo1 = 6 * M + (1 * M + o) * 4;
        int fo2 = 6 * M + (2 * M + o) * 4;
        out[fo0 + 0] = cn0.x; out[fo0 + 1] = cn0.y; out[fo0 + 2] = cn0.z; out[fo0 + 3] = cn0.w;
        out[fo1 + 0] = cn1.x; out[fo1 + 1] = cn1.y; out[fo1 + 2] = cn1.z; out[fo1 + 3] = cn1.w;
        out[fo2 + 0] = cn2.x; out[fo2 + 1] = cn2.y; out[fo2 + 2] = cn2.z; out[fo2 + 3] = cn2.w;

        out[6 * M + 3 * M * 4 + o] = vld ? 1.0f : 0.0f;
    }
}

// ---------------- launch ----------------
extern "C" void kernel_launch(void* const* d_in, const int* in_sizes, int n_in,
                              void* d_out, int out_size) {
    const float*  logits  = (const float*)d_in[0];
    const float4* boxreg  = (const float4*)d_in[1];
    const float4* trajreg = (const float4*)d_in[2];
    const float4* prop    = (const float4*)d_in[3];
    const void*   hp      = d_in[4];
    const void*   wp      = d_in[5];
    float* out = (float*)d_out;
    int N = in_sizes[0] / C;

    void* cnt_ptr = nullptr;
    cudaGetSymbolAddress(&cnt_ptr, d_cnt);
    cudaMemsetAsync(cnt_ptr, 0, NC * sizeof(int));

    int warps_per_block = 8;
    int blocks = (N + warps_per_block - 1) / warps_per_block;
    fused_cand<<<blocks, warps_per_block * 32>>>(logits, boxreg, prop, hp, wp, N);

    int smem = CAP * (int)(sizeof(unsigned long long) + sizeof(float4) + sizeof(float) + 1);
    cudaFuncSetAttribute(nms_out_kernel, cudaFuncAttributeMaxDynamicSharedMemorySize, smem);
    nms_out_kernel<<<NC, NMS_T, smem>>>(logits, boxreg, trajreg, prop, hp, wp, out, N);
}

// round 11
// speedup vs baseline: 1.1767x; 1.1767x over previous
#include <cuda_runtime.h>

#define NMAX 50000
#define C    91
#define NC   90
#define TT   3
#define NDET 100
#define CAP  2048
#define NMS_T 512
#define NEG_INF (__int_as_float(0xff800000))
#define BBOX_CLIP 4.135166556742356f   // log(1000/16)

// ---------------- scratch (static device globals; no allocation) ----------------
__device__ int    d_cnt[NC];
__device__ int    d_cidx [(size_t)NC * NMAX];
__device__ float  d_cscore[(size_t)NC * NMAX];
__device__ float4 d_cbox [(size_t)NC * NMAX];

// ---------------- helpers ----------------
__device__ __forceinline__ float read_dim(const void* p) {
    int v = *(const int*)p;
    if (v > 0 && v < 1000000) return (float)v;
    return *(const float*)p;
}

__device__ __forceinline__ float4 decode4(float4 d, float4 b) {
    float w  = b.z - b.x;
    float h  = b.w - b.y;
    float cx = b.x + 0.5f * w;
    float cy = b.y + 0.5f * h;
    float dx = d.x / 10.0f;
    float dy = d.y / 10.0f;
    float dw = fminf(d.z / 5.0f, BBOX_CLIP);
    float dh = fminf(d.w / 5.0f, BBOX_CLIP);
    float pcx = dx * w + cx;
    float pcy = dy * h + cy;
    float pw  = expf(dw) * w;
    float ph  = expf(dh) * h;
    float4 r;
    r.x = pcx - 0.5f * pw;
    r.y = pcy - 0.5f * ph;
    r.z = pcx + 0.5f * pw;
    r.w = pcy + 0.5f * ph;
    return r;
}

__device__ __forceinline__ float4 clip4(float4 b, float W, float H) {
    float4 r;
    r.x = fminf(fmaxf(b.x, 0.0f), W);
    r.y = fminf(fmaxf(b.y, 0.0f), H);
    r.z = fminf(fmaxf(b.z, 0.0f), W);
    r.w = fminf(fmaxf(b.w, 0.0f), H);
    return r;
}

__device__ __forceinline__ bool iou_gt(float4 c, float ac, float4 bb, float k1) {
    float lx = fmaxf(bb.x, c.x), ly = fmaxf(bb.y, c.y);
    float rx = fminf(bb.z, c.z), ry = fminf(bb.w, c.w);
    float iw = fmaxf(rx - lx, 0.0f), ih = fmaxf(ry - ly, 0.0f);
    float inter = iw * ih;
    float t = k1 + ac - inter;
    return inter + inter > t;        // iou > 0.5
}

// ---------------- kernel 1: fused softmax + filter + decode + compact ----------------
__global__ void __launch_bounds__(256, 8)
fused_cand(const float* __restrict__ logits,
           const float4* __restrict__ boxreg,   // [N, C] float4
           const float4* __restrict__ prop,     // [N]
           const void* hp, const void* wp, int N) {
    int warp = (blockIdx.x * blockDim.x + threadIdx.x) >> 5;
    int lane = threadIdx.x & 31;
    if (warp >= N) return;
    const float* row = logits + (size_t)warp * C;
    float v0 = row[lane];
    float v1 = row[lane + 32];
    float v2 = (lane < C - 64) ? row[lane + 64] : NEG_INF;
    float m = fmaxf(v0, fmaxf(v1, v2));
    #pragma unroll
    for (int o = 16; o; o >>= 1) m = fmaxf(m, __shfl_xor_sync(~0u, m, o));
    float e0 = expf(v0 - m);
    float e1 = expf(v1 - m);
    float e2 = (lane < C - 64) ? expf(v2 - m) : 0.0f;
    float s = e0 + e1 + e2;
    #pragma unroll
    for (int o = 16; o; o >>= 1) s += __shfl_xor_sync(~0u, s, o);

    // coarse filter (superset; exact recheck with identical FP expr below)
    float thr = 0.0499f * s;
    bool a0 = (lane >= 1) && (e0 >= thr);
    bool a1 = (e1 >= thr);
    bool a2 = (lane < C - 64) && (e2 >= thr);
    if (!__any_sync(~0u, a0 | a1 | a2)) return;

    float4 pr = prop[warp];
    float W = read_dim(wp), H = read_dim(hp);

    #pragma unroll
    for (int slot = 0; slot < 3; ++slot) {
        bool act = slot == 0 ? a0 : (slot == 1 ? a1 : a2);
        if (!act) continue;
        float e = slot == 0 ? e0 : (slot == 1 ? e1 : e2);
        float p = e / s;                 // exact
        if (p < 0.05f) continue;         // exact recheck
        int c = lane + 32 * slot;        // class index 1..90
        float4 cb = clip4(decode4(boxreg[(size_t)warp * C + c], pr), W, H);
        float ws = cb.z - cb.x, hs = cb.w - cb.y;
        if (ws < 1.0f || hs < 1.0f) continue;
        int j = c - 1;
        int sl = atomicAdd(&d_cnt[j], 1);
        size_t off = (size_t)j * NMAX + sl;
        d_cidx[off]   = warp;
        d_cscore[off] = p;
        d_cbox[off]   = cb;
    }
}

// ---------------- kernel 2: sorted windowed-bitmask NMS + fused output ----------------
__global__ void __launch_bounds__(NMS_T, 1)
nms_out_kernel(const float* __restrict__ logits,
               const float4* __restrict__ boxreg,
               const float4* __restrict__ trajreg,   // [T, N, C] float4
               const float4* __restrict__ prop,
               const void* hp, const void* wp,
               float* __restrict__ out, int N) {
    int j = blockIdx.x;
    int cnt = d_cnt[j];
    if (cnt > CAP) cnt = CAP;
    size_t base = (size_t)j * NMAX;
    int tid = threadIdx.x, lane = tid & 31, warp = tid >> 5;

    extern __shared__ unsigned char smem_raw[];
    unsigned long long* s_key = (unsigned long long*)smem_raw;        // CAP * 8
    float4* s_box  = (float4*)(s_key + CAP);                          // CAP * 16
    float*  s_area = (float*)(s_box + CAP);                           // CAP * 4
    unsigned char* s_supp = (unsigned char*)(s_area + CAP);           // CAP * 1

    __shared__ unsigned long long s_mat[64];
    __shared__ float4 s_pbox[64];
    __shared__ float  s_parea[64];
    __shared__ int    s_np, s_it;
    __shared__ int    s_keep[NDET];

    int it = 0;

    if (cnt > 0) {
        int n = 1;
        while (n < cnt) n <<= 1;
        if (n < 2) n = 2;

        // key: (score_bits << 32) | ~slot  -> desc sort: score desc, slot asc on ties
        for (int i = tid; i < n; i += NMS_T) {
            s_key[i] = (i < cnt)
                ? (((unsigned long long)__float_as_uint(d_cscore[base + i]) << 32)
                   | (unsigned)(~(unsigned)i))
                : 0ull;
        }

        // bitonic sort, descending; pair-index formulation.
        // st <= 32 phases are warp-private -> __syncwarp suffices.
        bool prev_big = true;   // key init wrote cross-warp
        for (int k = 2; k <= n; k <<= 1) {
            for (int st = k >> 1; st > 0; st >>= 1) {
                bool big = (st >= 64);
                if (big || prev_big) __syncthreads(); else __syncwarp();
                for (int p = tid; p < (n >> 1); p += NMS_T) {
                    int i = 2 * p - (p & (st - 1));
                    int l = i + st;
                    unsigned long long a = s_key[i], b = s_key[l];
                    bool desc = ((i & k) == 0);
                    if (desc ? (a < b) : (a > b)) { s_key[i] = b; s_key[l] = a; }
                }
                prev_big = big;
            }
        }
        __syncthreads();

        // gather boxes in sorted order
        for (int i = tid; i < cnt; i += NMS_T) {
            int sl = (int)(~(unsigned)(s_key[i] & 0xffffffffu));
            float4 b = d_cbox[base + sl];
            s_box[i]  = b;
            s_area[i] = (b.z - b.x) * (b.w - b.y);
            s_supp[i] = 0;
        }
        __syncthreads();

        // ------- windowed bitmask greedy NMS -------
        // invariant at window start: s_supp[i] for i >= w0 reflects all picks so far
        for (int w0 = 0; w0 < cnt && it < NDET; w0 += 64) {
            int m = cnt - w0; if (m > 64) m = 64;

            // 1. build in-window suppression matrix (reads only static boxes;
            //    safely overlaps the previous window's sweep)
            int i0 = w0 + lane;      int i0c = (i0 < cnt) ? i0 : (cnt - 1);
            int i1 = w0 + lane + 32; int i1c = (i1 < cnt) ? i1 : (cnt - 1);
            float4 c0 = s_box[i0c]; float a0 = s_area[i0c];
            float4 c1 = s_box[i1c]; float a1 = s_area[i1c];
            #pragma unroll
            for (int q = 0; q < 4; ++q) {
                int r = warp + (q << 4);
                if (r < m) {
                    int p = w0 + r;
                    float4 pb = s_box[p];
                    float  pk = s_area[p] + 1e-9f;
                    unsigned lo = __ballot_sync(~0u, iou_gt(c0, a0, pb, pk));
                    unsigned hi = __ballot_sync(~0u, iou_gt(c1, a1, pb, pk));
                    if (lane == 0)
                        s_mat[r] = (unsigned long long)lo
                                 | ((unsigned long long)hi << 32);
                }
            }
            __syncthreads();   // matrix ready AND previous sweep's s_supp visible

            // 2. resolve picks in this window (warp 0; lane 0 serial over bits)
            if (tid < 32) {
                unsigned lo = __ballot_sync(~0u, (lane < m) && (s_supp[w0 + lane] == 0));
                unsigned hi = __ballot_sync(~0u, (lane + 32 < m) && (s_supp[w0 + lane + 32] == 0));
                if (lane == 0) {
                    unsigned long long alive = (unsigned long long)lo
                                             | ((unsigned long long)hi << 32);
                    int np = 0, itl = it;
                    while (alive && itl < NDET) {
                        int a = __ffsll((long long)alive) - 1;
                        int p = w0 + a;
                        s_keep[itl] = (int)(~(unsigned)(s_key[p] & 0xffffffffu));
                        s_pbox[np]  = s_box[p];
                        s_parea[np] = s_area[p] + 1e-9f;
                        ++np; ++itl;
                        unsigned long long low =
                            (a >= 63) ? ~0ull : ((1ull << (a + 1)) - 1ull);
                        alive &= ~s_mat[a];
                        alive &= ~low;
                    }
                    s_np = np; s_it = itl;
                }
            }
            __syncthreads();   // picks visible
            it = s_it;
            int np = s_np;

            // 3. sweep tail vs this window's picks (dynamic loop, early break)
            if (it < NDET && np > 0) {
                for (int i = w0 + 64 + tid; i < cnt; i += NMS_T) {
                    if (!s_supp[i]) {
                        float4 c = s_box[i];
                        float ac = s_area[i];
                        for (int b = 0; b < np; ++b) {
                            if (iou_gt(c, ac, s_pbox[b], s_parea[b])) {
                                s_supp[i] = 1;
                                break;
                            }
                        }
                    }
                }
            }
        }
    }

    // exhausted: remaining slots invalid
    for (int r = it + tid; r < NDET; r += NMS_T) s_keep[r] = -1;
    __syncthreads();

    // ---------------- fused output phase ----------------
    float W = read_dim(wp), H = read_dim(hp);
    const int M = NC * NDET;
    for (int s = tid; s < NDET; s += NMS_T) {
        int o = j * NDET + s;
        int slot = s_keep[s];
        int k = (slot >= 0) ? d_cidx[base + slot] : 0;

        // independent gathers issued up front
        float4 pr  = prop[k];
        float4 td0 = trajreg[((size_t)0 * N + k) * C + (j + 1)];
        float4 td1 = trajreg[((size_t)1 * N + k) * C + (j + 1)];
        float4 td2 = trajreg[((size_t)2 * N + k) * C + (j + 1)];

        float4 cb; float p; int vld;
        if (slot >= 0) {
            cb  = d_cbox[base + slot];       // already clipped
            p   = d_cscore[base + slot];
            vld = 1;
        } else {
            cb = clip4(decode4(boxreg[j + 1], pr), W, H);
            const float* lg0 = logits;
            float mm = NEG_INF;
            for (int c = 0; c < C; ++c) mm = fmaxf(mm, lg0[c]);
            float ss = 0.0f;
            for (int c = 0; c < C; ++c) ss += expf(lg0[c] - mm);
            p = expf(lg0[j + 1] - mm) / ss;
            vld = 0;
        }

        out[o * 4 + 0] = cb.x;
        out[o * 4 + 1] = cb.y;
        out[o * 4 + 2] = cb.z;
        out[o * 4 + 3] = cb.w;
        out[4 * M + o] = (float)(j + 1);
        out[5 * M + o] = p;

        // trajectory chain: carry UNclipped, emit clipped
        float4 nb0 = decode4(td0, pr);
        float4 nb1 = decode4(td1, nb0);
        float4 nb2 = decode4(td2, nb1);
        float4 cn0 = clip4(nb0, W, H);
        float4 cn1 = clip4(nb1, W, H);
        float4 cn2 = clip4(nb2, W, H);
        int fo0 = 6 * M + (0 * M + o) * 4;
        int fo1 = 6 * M + (1 * M + o) * 4;
        int fo2 = 6 * M + (2 * M + o) * 4;
        out[fo0 + 0] = cn0.x; out[fo0 + 1] = cn0.y; out[fo0 + 2] = cn0.z; out[fo0 + 3] = cn0.w;
        out[fo1 + 0] = cn1.x; out[fo1 + 1] = cn1.y; out[fo1 + 2] = cn1.z; out[fo1 + 3] = cn1.w;
        out[fo2 + 0] = cn2.x; out[fo2 + 1] = cn2.y; out[fo2 + 2] = cn2.z; out[fo2 + 3] = cn2.w;

        out[6 * M + 3 * M * 4 + o] = vld ? 1.0f : 0.0f;
    }
}

// ---------------- launch ----------------
extern "C" void kernel_launch(void* const* d_in, const int* in_sizes, int n_in,
                              void* d_out, int out_size) {
    const float*  logits  = (const float*)d_in[0];
    const float4* boxreg  = (const float4*)d_in[1];
    const float4* trajreg = (const float4*)d_in[2];
    const float4* prop    = (const float4*)d_in[3];
    const void*   hp      = d_in[4];
    const void*   wp      = d_in[5];
    float* out = (float*)d_out;
    int N = in_sizes[0] / C;

    void* cnt_ptr = nullptr;
    cudaGetSymbolAddress(&cnt_ptr, d_cnt);
    cudaMemsetAsync(cnt_ptr, 0, NC * sizeof(int));

    int warps_per_block = 8;
    int blocks = (N + warps_per_block - 1) / warps_per_block;
    fused_cand<<<blocks, warps_per_block * 32>>>(logits, boxreg, prop, hp, wp, N);

    int smem = CAP * (int)(sizeof(unsigned long long) + sizeof(float4) + sizeof(float) + 1);
    cudaFuncSetAttribute(nms_out_kernel, cudaFuncAttributeMaxDynamicSharedMemorySize, smem);
    nms_out_kernel<<<NC, NMS_T, smem>>>(logits, boxreg, trajreg, prop, hp, wp, out, N);
}